// round 1
// baseline (speedup 1.0000x reference)
#include <cuda_runtime.h>
#include <math.h>

// Problem constants
#define NB   4
#define C    128
#define H    64
#define W    64
#define P    4096      // H*W
#define G    8
#define CG   16        // C/G
#define KK   9
#define OM   32
#define JOFF 256       // G*OM

// Scratch (static device globals — no allocation allowed)
__device__ float g_val [NB * P * C];     // (n, p, c)
__device__ float g_om  [NB * P * JOFF];  // (n, p, g*32+j)
__device__ float g_samp[NB * P * C];     // (n, p, c)

// ---------------------------------------------------------------------------
// GEMM 1/2: out[n,p,j] = sum_c x[n,c,p] * B[c,j] + bias[j]
// A is x viewed column-major (lda = P) -> loads along p are coalesced.
// Tile 64x64, BK=16, 256 threads, 4x4 microtile.
// which: 0 -> g_val (J=128), 1 -> g_om (J=256)
// ---------------------------------------------------------------------------
__global__ void gemm_xT_kernel(const float* __restrict__ x,
                               const float* __restrict__ B,
                               const float* __restrict__ bias,
                               int J, int which)
{
    __shared__ __align__(16) float As[16][64];
    __shared__ __align__(16) float Bs[16][64];

    const int n  = blockIdx.z;
    const int p0 = blockIdx.y * 64;
    const int j0 = blockIdx.x * 64;
    const float* xn = x + (size_t)n * C * P;
    float* outp = which ? g_om : g_val;

    const int t  = threadIdx.x;      // 0..255
    const int tx = t & 15;           // j microtile
    const int ty = t >> 4;           // p microtile

    float acc[4][4];
#pragma unroll
    for (int i = 0; i < 4; i++)
#pragma unroll
        for (int j = 0; j < 4; j++) acc[i][j] = 0.f;

    for (int k0 = 0; k0 < C; k0 += 16) {
#pragma unroll
        for (int l = 0; l < 4; l++) {
            int idx = t + l * 256;
            int kc = idx >> 6, m = idx & 63;
            As[kc][m] = xn[(size_t)(k0 + kc) * P + p0 + m];
            Bs[kc][m] = B[(size_t)(k0 + kc) * J + j0 + m];
        }
        __syncthreads();
#pragma unroll
        for (int kc = 0; kc < 16; kc++) {
            float4 a4 = *(const float4*)&As[kc][ty * 4];
            float4 b4 = *(const float4*)&Bs[kc][tx * 4];
            float av[4] = {a4.x, a4.y, a4.z, a4.w};
            float bv[4] = {b4.x, b4.y, b4.z, b4.w};
#pragma unroll
            for (int i = 0; i < 4; i++)
#pragma unroll
                for (int j = 0; j < 4; j++)
                    acc[i][j] += av[i] * bv[j];
        }
        __syncthreads();
    }

#pragma unroll
    for (int i = 0; i < 4; i++) {
        int p = p0 + ty * 4 + i;
        float4 r;
        r.x = acc[i][0] + bias[j0 + tx * 4 + 0];
        r.y = acc[i][1] + bias[j0 + tx * 4 + 1];
        r.z = acc[i][2] + bias[j0 + tx * 4 + 2];
        r.w = acc[i][3] + bias[j0 + tx * 4 + 3];
        *(float4*)&outp[(size_t)(n * P + p) * J + j0 + tx * 4] = r;
    }
}

// ---------------------------------------------------------------------------
// Deformable bilinear sampling. One thread per (n, p, g); 16 channels in
// 4 float4 accumulators. Out-of-bounds corners skipped (weight would be 0).
// ---------------------------------------------------------------------------
__global__ void sample_kernel()
{
    int tid = blockIdx.x * blockDim.x + threadIdx.x; // NB*P*G = 131072
    int g = tid & 7;
    int p = (tid >> 3) & (P - 1);
    int n = tid >> 15;

    const float* om = g_om + (size_t)(n * P + p) * JOFF + g * OM;
    const int h = p >> 6;
    const int w = p & 63;
    const float* valbase = g_val + (size_t)n * P * C + g * CG;

    float4 a0 = {0,0,0,0}, a1 = {0,0,0,0}, a2 = {0,0,0,0}, a3 = {0,0,0,0};

#pragma unroll
    for (int k = 0; k < KK; k++) {
        float ox = om[2 * k + 0];
        float oy = om[2 * k + 1];
        float m  = om[18 + k];
        float sy = (float)(h + k / 3 - 1) + oy;
        float sx = (float)(w + k % 3 - 1) + ox;
        float fy = floorf(sy), fx = floorf(sx);
        float tyf = sy - fy, txf = sx - fx;
        int y0 = (int)fy, x0 = (int)fx;

#pragma unroll
        for (int dy = 0; dy < 2; dy++) {
            int iy = y0 + dy;
            if (iy < 0 || iy >= H) continue;
            float wy = dy ? tyf : (1.f - tyf);
#pragma unroll
            for (int dx = 0; dx < 2; dx++) {
                int ix = x0 + dx;
                if (ix < 0 || ix >= W) continue;
                float wx = dx ? txf : (1.f - txf);
                float wgt = wy * wx * m;
                const float* v = valbase + (size_t)(iy * W + ix) * C;
                float4 v0 = *(const float4*)(v + 0);
                float4 v1 = *(const float4*)(v + 4);
                float4 v2 = *(const float4*)(v + 8);
                float4 v3 = *(const float4*)(v + 12);
                a0.x += v0.x * wgt; a0.y += v0.y * wgt; a0.z += v0.z * wgt; a0.w += v0.w * wgt;
                a1.x += v1.x * wgt; a1.y += v1.y * wgt; a1.z += v1.z * wgt; a1.w += v1.w * wgt;
                a2.x += v2.x * wgt; a2.y += v2.y * wgt; a2.z += v2.z * wgt; a2.w += v2.w * wgt;
                a3.x += v3.x * wgt; a3.y += v3.y * wgt; a3.z += v3.z * wgt; a3.w += v3.w * wgt;
            }
        }
    }

    float* o = g_samp + (size_t)(n * P + p) * C + g * CG;
    *(float4*)(o + 0)  = a0;
    *(float4*)(o + 4)  = a1;
    *(float4*)(o + 8)  = a2;
    *(float4*)(o + 12) = a3;
}

// ---------------------------------------------------------------------------
// GEMM 3 + bias + BN + SiLU, store transposed to (N,C,H,W).
// C'[p,c] = sum_k samp[p,k] * w_out[k,c]; microtile: tx -> p (for float4
// coalesced transposed store along p), ty -> c.
// ---------------------------------------------------------------------------
__global__ void gemm_out_kernel(const float* __restrict__ wout,
                                const float* __restrict__ bout,
                                const float* __restrict__ gamma,
                                const float* __restrict__ beta,
                                const float* __restrict__ mean,
                                const float* __restrict__ var,
                                float* __restrict__ out)
{
    __shared__ float As[16][65];                 // samp tile (padded vs conflicts)
    __shared__ __align__(16) float Bs[16][64];   // w_out tile

    const int n  = blockIdx.z;
    const int p0 = blockIdx.y * 64;
    const int c0 = blockIdx.x * 64;
    const float* samp = g_samp + (size_t)n * P * C;

    const int t  = threadIdx.x;
    const int tx = t & 15;   // p microtile
    const int ty = t >> 4;   // c microtile

    float acc[4][4];        // [j over c][i over p]
#pragma unroll
    for (int j = 0; j < 4; j++)
#pragma unroll
        for (int i = 0; i < 4; i++) acc[j][i] = 0.f;

    for (int k0 = 0; k0 < C; k0 += 16) {
        {   // A: row-major samp, float4 global loads; scatter to As[kc][pm]
            int pm = t >> 2;
            int kq = (t & 3) * 4;
            float4 v = *(const float4*)&samp[(size_t)(p0 + pm) * C + k0 + kq];
            As[kq + 0][pm] = v.x;
            As[kq + 1][pm] = v.y;
            As[kq + 2][pm] = v.z;
            As[kq + 3][pm] = v.w;
        }
#pragma unroll
        for (int l = 0; l < 4; l++) {
            int idx = t + l * 256;
            int kc = idx >> 6, m = idx & 63;
            Bs[kc][m] = wout[(size_t)(k0 + kc) * C + c0 + m];
        }
        __syncthreads();
#pragma unroll
        for (int kc = 0; kc < 16; kc++) {
            float av[4];
#pragma unroll
            for (int i = 0; i < 4; i++) av[i] = As[kc][tx * 4 + i];
            float4 b4 = *(const float4*)&Bs[kc][ty * 4];
            float bv[4] = {b4.x, b4.y, b4.z, b4.w};
#pragma unroll
            for (int j = 0; j < 4; j++)
#pragma unroll
                for (int i = 0; i < 4; i++)
                    acc[j][i] += bv[j] * av[i];
        }
        __syncthreads();
    }

#pragma unroll
    for (int j = 0; j < 4; j++) {
        int c = c0 + ty * 4 + j;
        float inv = gamma[c] * rsqrtf(var[c] + 1e-5f);
        float add = beta[c] - mean[c] * inv;
        float bo  = bout[c];
        float4 r;
        float vv[4];
#pragma unroll
        for (int i = 0; i < 4; i++) {
            float v = acc[j][i] + bo;
            v = v * inv + add;
            vv[i] = v / (1.f + expf(-v));   // SiLU
        }
        r.x = vv[0]; r.y = vv[1]; r.z = vv[2]; r.w = vv[3];
        *(float4*)&out[(size_t)(n * C + c) * P + p0 + tx * 4] = r;
    }
}

// ---------------------------------------------------------------------------
extern "C" void kernel_launch(void* const* d_in, const int* in_sizes, int n_in,
                              void* d_out, int out_size)
{
    const float* x       = (const float*)d_in[0];
    const float* w_value = (const float*)d_in[1];
    const float* b_value = (const float*)d_in[2];
    const float* w_off   = (const float*)d_in[3];
    const float* b_off   = (const float*)d_in[4];
    const float* w_out   = (const float*)d_in[5];
    const float* b_out   = (const float*)d_in[6];
    const float* gamma   = (const float*)d_in[7];
    const float* beta    = (const float*)d_in[8];
    const float* mean    = (const float*)d_in[9];
    const float* var     = (const float*)d_in[10];
    float* out = (float*)d_out;

    dim3 blk(256);
    // val = xf @ w_value + b_value  (J=128)
    gemm_xT_kernel<<<dim3(C / 64, P / 64, NB), blk>>>(x, w_value, b_value, C, 0);
    // om = xf @ w_off + b_off       (J=256)
    gemm_xT_kernel<<<dim3(JOFF / 64, P / 64, NB), blk>>>(x, w_off, b_off, JOFF, 1);
    // deformable bilinear sampling
    sample_kernel<<<(NB * P * G) / 128, 128>>>();
    // out GEMM + bias + BN + SiLU, transposed store
    gemm_out_kernel<<<dim3(C / 64, P / 64, NB), blk>>>(w_out, b_out, gamma, beta,
                                                       mean, var, out);
}

// round 3
// speedup vs baseline: 1.2014x; 1.2014x over previous
#include <cuda_runtime.h>
#include <cuda_bf16.h>
#include <math.h>
#include <stdint.h>

// Problem constants
#define NB   4
#define C    128
#define H    64
#define W    64
#define P    4096
#define G    8
#define CG   16
#define KK   9
#define OMC  32
#define JOFF 256
#define MTOT (NB*P)       // 16384

// ---------------------------------------------------------------------------
// Scratch
// ---------------------------------------------------------------------------
__device__ float g_val [NB * P * C];
__device__ float g_om  [NB * P * JOFF];
__device__ float g_samp[NB * P * C];

// bf16 hi/lo weight images, plain row-major [k][j]
__device__ __nv_bfloat16 g_Bv_hi[128*128], g_Bv_lo[128*128];
__device__ __nv_bfloat16 g_Bo_hi[128*256], g_Bo_lo[128*256];
__device__ __nv_bfloat16 g_Bw_hi[128*128], g_Bw_lo[128*128];

// ---------------------------------------------------------------------------
// smem layout: padded bf16 tiles, stride 136 elems (272 B rows, 16B-aligned,
// conflict-free for ldmatrix: row-to-row bank offset = 4)
// ---------------------------------------------------------------------------
#define STRA 136
#define TILEB (128 * STRA * 2)     // 34816 bytes
#define SM_AH 0
#define SM_AL (TILEB)
#define SM_BH (2 * TILEB)
#define SM_BL (3 * TILEB)
#define SM_TOTAL (4 * TILEB)       // 139264 bytes

__device__ __forceinline__ uint32_t smem_u32(const void* p) {
    uint32_t a;
    asm("{ .reg .u64 t; cvta.to.shared.u64 t, %1; cvt.u32.u64 %0, t; }" : "=r"(a) : "l"(p));
    return a;
}

#define LDSM_X4(r, a) \
    asm volatile("ldmatrix.sync.aligned.m8n8.x4.shared.b16 {%0,%1,%2,%3}, [%4];" \
        : "=r"((r)[0]), "=r"((r)[1]), "=r"((r)[2]), "=r"((r)[3]) : "r"(a))

#define LDSM_X4T(r0, r1, r2, r3, a) \
    asm volatile("ldmatrix.sync.aligned.m8n8.x4.trans.shared.b16 {%0,%1,%2,%3}, [%4];" \
        : "=r"(r0), "=r"(r1), "=r"(r2), "=r"(r3) : "r"(a))

__device__ __forceinline__ void mma16816(float* d, const uint32_t* a, const uint32_t* b) {
    asm volatile(
        "mma.sync.aligned.m16n8k16.row.col.f32.bf16.bf16.f32 "
        "{%0,%1,%2,%3}, {%4,%5,%6,%7}, {%8,%9}, {%0,%1,%2,%3};"
        : "+f"(d[0]), "+f"(d[1]), "+f"(d[2]), "+f"(d[3])
        : "r"(a[0]), "r"(a[1]), "r"(a[2]), "r"(a[3]), "r"(b[0]), "r"(b[1]));
}

__device__ __forceinline__ uint32_t pack_bf16(float a, float b) {
    __nv_bfloat162 h2 = __halves2bfloat162(__float2bfloat16(a), __float2bfloat16(b));
    return *reinterpret_cast<uint32_t*>(&h2);
}

// ---------------------------------------------------------------------------
// Prep: fp32 weights -> bf16 hi/lo images (plain row-major)
// ---------------------------------------------------------------------------
__global__ void prep_kernel(const float* __restrict__ wv,
                            const float* __restrict__ wo,
                            const float* __restrict__ ww)
{
    int t = blockIdx.x * blockDim.x + threadIdx.x;  // 65536 total
    const float* src; __nv_bfloat16 *dh, *dl; int e;
    if (t < 16384)      { src = wv; dh = g_Bv_hi; dl = g_Bv_lo; e = t;         }
    else if (t < 49152) { src = wo; dh = g_Bo_hi; dl = g_Bo_lo; e = t - 16384; }
    else                { src = ww; dh = g_Bw_hi; dl = g_Bw_lo; e = t - 49152; }
    float v = src[e];
    __nv_bfloat16 h = __float2bfloat16(v);
    dh[e] = h;
    dl[e] = __float2bfloat16(v - __bfloat162float(h));
}

// ---------------------------------------------------------------------------
// Shared GEMM core: 128x128 CTA tile, K=128, 8 warps (2m x 4n), warp 64x32.
// Split-3: AH*BH + AH*BL + AL*BH into same fp32 accumulators.
// acc[mi][nt][4]
// ---------------------------------------------------------------------------
__device__ __forceinline__ void gemm_core(uint32_t smb, int lane, int wid,
                                          float acc[4][4][4])
{
    const int wm = wid & 1, wn = wid >> 1;
    const int mbase = wm * 64, nbase = wn * 32;

    const uint32_t aoffs[3] = {SM_AH, SM_AH, SM_AL};
    const uint32_t boffs[3] = {SM_BH, SM_BL, SM_BH};

#pragma unroll
    for (int pass = 0; pass < 3; pass++) {
        const uint32_t abase = smb + aoffs[pass];
        const uint32_t bbase = smb + boffs[pass];
#pragma unroll
        for (int kk = 0; kk < 8; kk++) {
            const int k0 = kk * 16;
            uint32_t a[4][4];
#pragma unroll
            for (int mi = 0; mi < 4; mi++) {
                int mrow = mbase + mi * 16 + (lane & 15);
                uint32_t addr = abase + (uint32_t)(mrow * STRA + k0 + (lane >> 4) * 8) * 2;
                LDSM_X4(a[mi], addr);
            }
            uint32_t b[4][2];
#pragma unroll
            for (int bj = 0; bj < 2; bj++) {
                int krow = k0 + (lane & 15);
                int ncol = nbase + bj * 16 + (lane >> 4) * 8;
                uint32_t addr = bbase + (uint32_t)(krow * STRA + ncol) * 2;
                LDSM_X4T(b[bj*2][0], b[bj*2][1], b[bj*2+1][0], b[bj*2+1][1], addr);
            }
#pragma unroll
            for (int mi = 0; mi < 4; mi++)
#pragma unroll
                for (int nt = 0; nt < 4; nt++)
                    mma16816(acc[mi][nt], a[mi], b[nt]);
        }
    }
}

// Copy a 128x128 bf16 weight tile (row stride J, col offset n0) into padded smem
__device__ __forceinline__ void load_B(char* sm, int smoff,
                                       const __nv_bfloat16* __restrict__ B,
                                       int J, int n0, int t)
{
    for (int i = t; i < 128 * 16; i += 256) {
        int row = i >> 4, q = i & 15;
        const uint4* src = (const uint4*)(B + (size_t)row * J + n0) + q;
        uint4* dst = (uint4*)(sm + smoff + row * (STRA * 2)) + q;
        *dst = *src;
    }
}

// ---------------------------------------------------------------------------
// GEMM 1/2: out[m, n0:n0+128] = x^T[m,:] @ Wt[:, n0:n0+128] + bias
// ---------------------------------------------------------------------------
__global__ __launch_bounds__(256, 1)
void gemm_x_kernel(const float* __restrict__ x,
                   const __nv_bfloat16* __restrict__ Bh,
                   const __nv_bfloat16* __restrict__ Bl,
                   const float* __restrict__ bias,
                   float* __restrict__ outp, int J)
{
    extern __shared__ char sm[];
    uint32_t smb = smem_u32(sm);
    const int t = threadIdx.x, lane = t & 31, wid = t >> 5;

    const int mg0 = blockIdx.x * 128;
    const int n0  = blockIdx.y * 128;
    const int nimg = mg0 >> 12;
    const int p0   = mg0 & 4095;
    const float* xn = x + (size_t)nimg * C * P + p0;

    // --- A: x^T tile -> bf16 hi/lo (transpose: m=p, k=c) ---
    {
        const int m = t & 127, ch = t >> 7;
#pragma unroll 4
        for (int i = 0; i < 32; i++) {
            int c = (i * 2 + ch) * 2;
            float v0 = xn[(size_t)c * P + m];
            float v1 = xn[(size_t)(c + 1) * P + m];
            float h0 = __bfloat162float(__float2bfloat16(v0));
            float h1 = __bfloat162float(__float2bfloat16(v1));
            uint32_t off = (uint32_t)(m * STRA + c) * 2;
            *(uint32_t*)(sm + SM_AH + off) = pack_bf16(h0, h1);
            *(uint32_t*)(sm + SM_AL + off) = pack_bf16(v0 - h0, v1 - h1);
        }
    }
    load_B(sm, SM_BH, Bh, J, n0, t);
    load_B(sm, SM_BL, Bl, J, n0, t);
    __syncthreads();

    float acc[4][4][4];
#pragma unroll
    for (int a = 0; a < 4; a++)
#pragma unroll
        for (int b = 0; b < 4; b++)
#pragma unroll
            for (int r = 0; r < 4; r++) acc[a][b][r] = 0.f;

    gemm_core(smb, lane, wid, acc);

    // --- epilogue: + bias, float2 stores ---
    const int wm = wid & 1, wn = wid >> 1;
    const int gid = lane >> 2, tg = lane & 3;
#pragma unroll
    for (int mi = 0; mi < 4; mi++) {
        int mrow = mg0 + wm * 64 + mi * 16 + gid;
#pragma unroll
        for (int nt = 0; nt < 4; nt++) {
            int col = n0 + wn * 32 + nt * 8 + 2 * tg;
            float bs0 = __ldg(&bias[col]), bs1 = __ldg(&bias[col + 1]);
            float2 r0 = {acc[mi][nt][0] + bs0, acc[mi][nt][1] + bs1};
            float2 r1 = {acc[mi][nt][2] + bs0, acc[mi][nt][3] + bs1};
            *(float2*)&outp[(size_t)mrow * J + col] = r0;
            *(float2*)&outp[(size_t)(mrow + 8) * J + col] = r1;
        }
    }
}

// ---------------------------------------------------------------------------
// Deformable bilinear sampling
// ---------------------------------------------------------------------------
__global__ void sample_kernel()
{
    int tid = blockIdx.x * blockDim.x + threadIdx.x;
    int g = tid & 7;
    int p = (tid >> 3) & (P - 1);
    int n = tid >> 15;

    const float* om = g_om + (size_t)(n * P + p) * JOFF + g * OMC;
    const int h = p >> 6;
    const int w = p & 63;
    const float* valbase = g_val + (size_t)n * P * C + g * CG;

    float4 a0 = {0,0,0,0}, a1 = {0,0,0,0}, a2 = {0,0,0,0}, a3 = {0,0,0,0};

#pragma unroll
    for (int k = 0; k < KK; k++) {
        float ox = om[2 * k + 0];
        float oy = om[2 * k + 1];
        float m  = om[18 + k];
        float sy = (float)(h + k / 3 - 1) + oy;
        float sx = (float)(w + k % 3 - 1) + ox;
        float fy = floorf(sy), fx = floorf(sx);
        float tyf = sy - fy, txf = sx - fx;
        int y0 = (int)fy, x0 = (int)fx;

#pragma unroll
        for (int dy = 0; dy < 2; dy++) {
            int iy = y0 + dy;
            if (iy < 0 || iy >= H) continue;
            float wy = dy ? tyf : (1.f - tyf);
#pragma unroll
            for (int dx = 0; dx < 2; dx++) {
                int ix = x0 + dx;
                if (ix < 0 || ix >= W) continue;
                float wx = dx ? txf : (1.f - txf);
                float wgt = wy * wx * m;
                const float* v = valbase + (size_t)(iy * W + ix) * C;
                float4 v0 = *(const float4*)(v + 0);
                float4 v1 = *(const float4*)(v + 4);
                float4 v2 = *(const float4*)(v + 8);
                float4 v3 = *(const float4*)(v + 12);
                a0.x += v0.x * wgt; a0.y += v0.y * wgt; a0.z += v0.z * wgt; a0.w += v0.w * wgt;
                a1.x += v1.x * wgt; a1.y += v1.y * wgt; a1.z += v1.z * wgt; a1.w += v1.w * wgt;
                a2.x += v2.x * wgt; a2.y += v2.y * wgt; a2.z += v2.z * wgt; a2.w += v2.w * wgt;
                a3.x += v3.x * wgt; a3.y += v3.y * wgt; a3.z += v3.z * wgt; a3.w += v3.w * wgt;
            }
        }
    }

    float* o = g_samp + (size_t)(n * P + p) * C + g * CG;
    *(float4*)(o + 0)  = a0;
    *(float4*)(o + 4)  = a1;
    *(float4*)(o + 8)  = a2;
    *(float4*)(o + 12) = a3;
}

// ---------------------------------------------------------------------------
// GEMM 3 + bias + BN + SiLU, transposed store to (N,C,H,W)
// ---------------------------------------------------------------------------
__global__ __launch_bounds__(256, 1)
void gemm_out_kernel(const float* __restrict__ bout,
                     const float* __restrict__ gamma,
                     const float* __restrict__ beta,
                     const float* __restrict__ mean,
                     const float* __restrict__ var,
                     float* __restrict__ outp)
{
    extern __shared__ char sm[];
    uint32_t smb = smem_u32(sm);
    const int t = threadIdx.x, lane = t & 31, wid = t >> 5;
    const int mg0 = blockIdx.x * 128;

    // --- A: samp tile row-major -> bf16 hi/lo ---
    {
        const float* sa = g_samp + (size_t)mg0 * C;
#pragma unroll 4
        for (int i = t; i < 128 * 32; i += 256) {
            int m = i >> 5, kq = (i & 31) * 4;
            float4 v = *(const float4*)(sa + (size_t)m * C + kq);
            float hx = __bfloat162float(__float2bfloat16(v.x));
            float hy = __bfloat162float(__float2bfloat16(v.y));
            float hz = __bfloat162float(__float2bfloat16(v.z));
            float hw = __bfloat162float(__float2bfloat16(v.w));
            uint2 hp, lp;
            hp.x = pack_bf16(hx, hy);            hp.y = pack_bf16(hz, hw);
            lp.x = pack_bf16(v.x - hx, v.y - hy); lp.y = pack_bf16(v.z - hz, v.w - hw);
            uint32_t off = (uint32_t)(m * STRA + kq) * 2;
            *(uint2*)(sm + SM_AH + off) = hp;
            *(uint2*)(sm + SM_AL + off) = lp;
        }
    }
    load_B(sm, SM_BH, g_Bw_hi, 128, 0, t);
    load_B(sm, SM_BL, g_Bw_lo, 128, 0, t);
    __syncthreads();

    float acc[4][4][4];
#pragma unroll
    for (int a = 0; a < 4; a++)
#pragma unroll
        for (int b = 0; b < 4; b++)
#pragma unroll
            for (int r = 0; r < 4; r++) acc[a][b][r] = 0.f;

    gemm_core(smb, lane, wid, acc);

    // --- epilogue: bias + BN + SiLU, transposed store ---
    const int wm = wid & 1, wn = wid >> 1;
    const int gid = lane >> 2, tg = lane & 3;
    const int nimg = mg0 >> 12;
    const int pbase = (mg0 & 4095) + wm * 64;

#pragma unroll
    for (int nt = 0; nt < 4; nt++) {
        int c = wn * 32 + nt * 8 + 2 * tg;
        float iv0 = __ldg(&gamma[c])   * rsqrtf(__ldg(&var[c])   + 1e-5f);
        float iv1 = __ldg(&gamma[c+1]) * rsqrtf(__ldg(&var[c+1]) + 1e-5f);
        float ad0 = __ldg(&beta[c])   - __ldg(&mean[c])   * iv0;
        float ad1 = __ldg(&beta[c+1]) - __ldg(&mean[c+1]) * iv1;
        float bo0 = __ldg(&bout[c]), bo1 = __ldg(&bout[c+1]);
        float* out0 = outp + (size_t)(nimg * C + c)     * P;
        float* out1 = outp + (size_t)(nimg * C + c + 1) * P;
#pragma unroll
        for (int mi = 0; mi < 4; mi++) {
            int p = pbase + mi * 16 + gid;
            float v00 = (acc[mi][nt][0] + bo0) * iv0 + ad0;
            float v01 = (acc[mi][nt][1] + bo1) * iv1 + ad1;
            float v10 = (acc[mi][nt][2] + bo0) * iv0 + ad0;
            float v11 = (acc[mi][nt][3] + bo1) * iv1 + ad1;
            out0[p]     = v00 / (1.f + expf(-v00));
            out1[p]     = v01 / (1.f + expf(-v01));
            out0[p + 8] = v10 / (1.f + expf(-v10));
            out1[p + 8] = v11 / (1.f + expf(-v11));
        }
    }
}

// ---------------------------------------------------------------------------
extern "C" void kernel_launch(void* const* d_in, const int* in_sizes, int n_in,
                              void* d_out, int out_size)
{
    const float* x       = (const float*)d_in[0];
    const float* w_value = (const float*)d_in[1];
    const float* b_value = (const float*)d_in[2];
    const float* w_off   = (const float*)d_in[3];
    const float* b_off   = (const float*)d_in[4];
    const float* w_out   = (const float*)d_in[5];
    const float* b_out   = (const float*)d_in[6];
    const float* gamma   = (const float*)d_in[7];
    const float* beta    = (const float*)d_in[8];
    const float* mean    = (const float*)d_in[9];
    const float* var     = (const float*)d_in[10];
    float* out = (float*)d_out;

    cudaFuncSetAttribute(gemm_x_kernel,   cudaFuncAttributeMaxDynamicSharedMemorySize, SM_TOTAL);
    cudaFuncSetAttribute(gemm_out_kernel, cudaFuncAttributeMaxDynamicSharedMemorySize, SM_TOTAL);

    __nv_bfloat16 *bvh, *bvl, *boh, *bol, *bwh, *bwl;
    cudaGetSymbolAddress((void**)&bvh, g_Bv_hi);
    cudaGetSymbolAddress((void**)&bvl, g_Bv_lo);
    cudaGetSymbolAddress((void**)&boh, g_Bo_hi);
    cudaGetSymbolAddress((void**)&bol, g_Bo_lo);
    cudaGetSymbolAddress((void**)&bwh, g_Bw_hi);
    cudaGetSymbolAddress((void**)&bwl, g_Bw_lo);
    float *gval, *gom;
    cudaGetSymbolAddress((void**)&gval, g_val);
    cudaGetSymbolAddress((void**)&gom,  g_om);

    prep_kernel<<<256, 256>>>(w_value, w_off, w_out);
    gemm_x_kernel<<<dim3(MTOT/128, 1), 256, SM_TOTAL>>>(x, bvh, bvl, b_value, gval, 128);
    gemm_x_kernel<<<dim3(MTOT/128, 2), 256, SM_TOTAL>>>(x, boh, bol, b_off, gom, 256);
    sample_kernel<<<(NB * P * G) / 128, 128>>>();
    gemm_out_kernel<<<MTOT/128, 256, SM_TOTAL>>>(b_out, gamma, beta, mean, var, out);
}

// round 6
// speedup vs baseline: 1.6436x; 1.3680x over previous
#include <cuda_runtime.h>
#include <cuda_bf16.h>
#include <math.h>
#include <stdint.h>

// Problem constants
#define NB   4
#define C    128
#define H    64
#define W    64
#define P    4096
#define G    8
#define CG   16
#define KK   9
#define OMC  32
#define JOFF 256
#define MTOT (NB*P)       // 16384

// ---------------------------------------------------------------------------
// Scratch
// ---------------------------------------------------------------------------
__device__ float g_val [NB * P * C];
__device__ float g_om  [NB * P * JOFF];
__device__ float g_samp[NB * P * C];

// bf16 hi/lo weight images, plain row-major [k][j]
__device__ __nv_bfloat16 g_Bv_hi[128*128], g_Bv_lo[128*128];
__device__ __nv_bfloat16 g_Bo_hi[128*256], g_Bo_lo[128*256];
__device__ __nv_bfloat16 g_Bw_hi[128*128], g_Bw_lo[128*128];

// ---------------------------------------------------------------------------
// smem layout: padded bf16 tiles, stride 136 elems (272 B rows, 16B-aligned,
// conflict-free for ldmatrix: row-to-row bank offset = 4)
// ---------------------------------------------------------------------------
#define STRA 136
#define TILEB (128 * STRA * 2)     // 34816 bytes
#define SM_AH 0
#define SM_AL (TILEB)
#define SM_BH (2 * TILEB)
#define SM_BL (3 * TILEB)
#define SM_TOTAL (4 * TILEB)       // 139264 bytes

__device__ __forceinline__ uint32_t smem_u32(const void* p) {
    uint32_t a;
    asm("{ .reg .u64 t; cvta.to.shared.u64 t, %1; cvt.u32.u64 %0, t; }" : "=r"(a) : "l"(p));
    return a;
}

#define LDSM_X4(r, a) \
    asm volatile("ldmatrix.sync.aligned.m8n8.x4.shared.b16 {%0,%1,%2,%3}, [%4];" \
        : "=r"((r)[0]), "=r"((r)[1]), "=r"((r)[2]), "=r"((r)[3]) : "r"(a))

#define LDSM_X4T(r0, r1, r2, r3, a) \
    asm volatile("ldmatrix.sync.aligned.m8n8.x4.trans.shared.b16 {%0,%1,%2,%3}, [%4];" \
        : "=r"(r0), "=r"(r1), "=r"(r2), "=r"(r3) : "r"(a))

__device__ __forceinline__ void mma16816(float* d, const uint32_t* a, const uint32_t* b) {
    asm volatile(
        "mma.sync.aligned.m16n8k16.row.col.f32.bf16.bf16.f32 "
        "{%0,%1,%2,%3}, {%4,%5,%6,%7}, {%8,%9}, {%0,%1,%2,%3};"
        : "+f"(d[0]), "+f"(d[1]), "+f"(d[2]), "+f"(d[3])
        : "r"(a[0]), "r"(a[1]), "r"(a[2]), "r"(a[3]), "r"(b[0]), "r"(b[1]));
}

__device__ __forceinline__ uint32_t pack_bf16(float a, float b) {
    __nv_bfloat162 h2 = __halves2bfloat162(__float2bfloat16(a), __float2bfloat16(b));
    return *reinterpret_cast<uint32_t*>(&h2);
}

// ---------------------------------------------------------------------------
// Prep: fp32 weights -> bf16 hi/lo images (plain row-major)
// ---------------------------------------------------------------------------
__global__ void prep_kernel(const float* __restrict__ wv,
                            const float* __restrict__ wo,
                            const float* __restrict__ ww)
{
    int t = blockIdx.x * blockDim.x + threadIdx.x;  // 65536 total
    const float* src; __nv_bfloat16 *dh, *dl; int e;
    if (t < 16384)      { src = wv; dh = g_Bv_hi; dl = g_Bv_lo; e = t;         }
    else if (t < 49152) { src = wo; dh = g_Bo_hi; dl = g_Bo_lo; e = t - 16384; }
    else                { src = ww; dh = g_Bw_hi; dl = g_Bw_lo; e = t - 49152; }
    float v = src[e];
    __nv_bfloat16 h = __float2bfloat16(v);
    dh[e] = h;
    dl[e] = __float2bfloat16(v - __bfloat162float(h));
}

// ---------------------------------------------------------------------------
// Shared GEMM core: 128x128 CTA tile, K=128, 8 warps (2m x 4n), warp 64x32.
// Split-3: AH*BH + AH*BL + AL*BH into same fp32 accumulators.
// ---------------------------------------------------------------------------
__device__ __forceinline__ void gemm_core(uint32_t smb, int lane, int wid,
                                          float acc[4][4][4])
{
    const int wm = wid & 1, wn = wid >> 1;
    const int mbase = wm * 64, nbase = wn * 32;

    const uint32_t aoffs[3] = {SM_AH, SM_AH, SM_AL};
    const uint32_t boffs[3] = {SM_BH, SM_BL, SM_BH};

#pragma unroll
    for (int pass = 0; pass < 3; pass++) {
        const uint32_t abase = smb + aoffs[pass];
        const uint32_t bbase = smb + boffs[pass];
#pragma unroll
        for (int kk = 0; kk < 8; kk++) {
            const int k0 = kk * 16;
            uint32_t a[4][4];
#pragma unroll
            for (int mi = 0; mi < 4; mi++) {
                int mrow = mbase + mi * 16 + (lane & 15);
                uint32_t addr = abase + (uint32_t)(mrow * STRA + k0 + (lane >> 4) * 8) * 2;
                LDSM_X4(a[mi], addr);
            }
            uint32_t b[4][2];
#pragma unroll
            for (int bj = 0; bj < 2; bj++) {
                int krow = k0 + (lane & 15);
                int ncol = nbase + bj * 16 + (lane >> 4) * 8;
                uint32_t addr = bbase + (uint32_t)(krow * STRA + ncol) * 2;
                LDSM_X4T(b[bj*2][0], b[bj*2][1], b[bj*2+1][0], b[bj*2+1][1], addr);
            }
#pragma unroll
            for (int mi = 0; mi < 4; mi++)
#pragma unroll
                for (int nt = 0; nt < 4; nt++)
                    mma16816(acc[mi][nt], a[mi], b[nt]);
        }
    }
}

// Copy a 128x128 bf16 weight tile (row stride J, col offset n0) into padded smem
__device__ __forceinline__ void load_B(char* sm, int smoff,
                                       const __nv_bfloat16* __restrict__ B,
                                       int J, int n0, int t)
{
    for (int i = t; i < 128 * 16; i += 256) {
        int row = i >> 4, q = i & 15;
        const uint4* src = (const uint4*)(B + (size_t)row * J + n0) + q;
        uint4* dst = (uint4*)(sm + smoff + row * (STRA * 2)) + q;
        *dst = *src;
    }
}

// ---------------------------------------------------------------------------
// GEMM 1/2: out[m, n0:n0+128] = x^T[m,:] @ Wt[:, n0:n0+128] + bias
// ---------------------------------------------------------------------------
__global__ __launch_bounds__(256, 1)
void gemm_x_kernel(const float* __restrict__ x,
                   const __nv_bfloat16* __restrict__ Bh,
                   const __nv_bfloat16* __restrict__ Bl,
                   const float* __restrict__ bias,
                   float* __restrict__ outp, int J)
{
    extern __shared__ char sm[];
    uint32_t smb = smem_u32(sm);
    const int t = threadIdx.x, lane = t & 31, wid = t >> 5;

    const int mg0 = blockIdx.x * 128;
    const int n0  = blockIdx.y * 128;
    const int nimg = mg0 >> 12;
    const int p0   = mg0 & 4095;
    const float* xn = x + (size_t)nimg * C * P + p0;

    // --- A: x^T tile -> bf16 hi/lo (transpose: m=p, k=c) ---
    {
        const int m = t & 127, ch = t >> 7;
#pragma unroll 4
        for (int i = 0; i < 32; i++) {
            int c = (i * 2 + ch) * 2;
            float v0 = xn[(size_t)c * P + m];
            float v1 = xn[(size_t)(c + 1) * P + m];
            float h0 = __bfloat162float(__float2bfloat16(v0));
            float h1 = __bfloat162float(__float2bfloat16(v1));
            uint32_t off = (uint32_t)(m * STRA + c) * 2;
            *(uint32_t*)(sm + SM_AH + off) = pack_bf16(h0, h1);
            *(uint32_t*)(sm + SM_AL + off) = pack_bf16(v0 - h0, v1 - h1);
        }
    }
    load_B(sm, SM_BH, Bh, J, n0, t);
    load_B(sm, SM_BL, Bl, J, n0, t);
    __syncthreads();

    float acc[4][4][4];
#pragma unroll
    for (int a = 0; a < 4; a++)
#pragma unroll
        for (int b = 0; b < 4; b++)
#pragma unroll
            for (int r = 0; r < 4; r++) acc[a][b][r] = 0.f;

    gemm_core(smb, lane, wid, acc);

    // --- epilogue: + bias, float2 stores ---
    const int wm = wid & 1, wn = wid >> 1;
    const int gid = lane >> 2, tg = lane & 3;
#pragma unroll
    for (int mi = 0; mi < 4; mi++) {
        int mrow = mg0 + wm * 64 + mi * 16 + gid;
#pragma unroll
        for (int nt = 0; nt < 4; nt++) {
            int col = n0 + wn * 32 + nt * 8 + 2 * tg;
            float bs0 = __ldg(&bias[col]), bs1 = __ldg(&bias[col + 1]);
            float2 r0 = {acc[mi][nt][0] + bs0, acc[mi][nt][1] + bs1};
            float2 r1 = {acc[mi][nt][2] + bs0, acc[mi][nt][3] + bs1};
            *(float2*)&outp[(size_t)mrow * J + col] = r0;
            *(float2*)&outp[(size_t)(mrow + 8) * J + col] = r1;
        }
    }
}

// ---------------------------------------------------------------------------
// Deformable bilinear sampling — 4-lane cooperative channel split.
// Thread = (n, p, g, cq); lanes 4q..4q+3 share (p,g) and each handle 4
// channels, so every corner read is ONE LDG.128 into a 64B-contiguous block
// across the 4 lanes (~4x fewer L1 wavefronts than 4 scattered LDG.128).
// ---------------------------------------------------------------------------
__global__ __launch_bounds__(256)
void sample_kernel()
{
    int tid = blockIdx.x * blockDim.x + threadIdx.x; // NB*P*G*4 = 524288
    int cq = tid & 3;
    int g  = (tid >> 2) & 7;
    int p  = (tid >> 5) & (P - 1);
    int n  = tid >> 17;

    const float* om = g_om + (size_t)(n * P + p) * JOFF + g * OMC;
    const int h = p >> 6;
    const int w = p & 63;
    const float* valbase = g_val + (size_t)n * P * C + g * CG + cq * 4;

    float4 acc = {0.f, 0.f, 0.f, 0.f};

#pragma unroll
    for (int k = 0; k < KK; k++) {
        float ox = __ldg(&om[2 * k + 0]);
        float oy = __ldg(&om[2 * k + 1]);
        float m  = __ldg(&om[18 + k]);
        float sy = (float)(h + k / 3 - 1) + oy;
        float sx = (float)(w + k % 3 - 1) + ox;
        float fy = floorf(sy), fx = floorf(sx);
        float tyf = sy - fy, txf = sx - fx;
        int y0 = (int)fy, x0 = (int)fx;

#pragma unroll
        for (int dy = 0; dy < 2; dy++) {
            int iy = y0 + dy;
            if (iy < 0 || iy >= H) continue;
            float wy = dy ? tyf : (1.f - tyf);
#pragma unroll
            for (int dx = 0; dx < 2; dx++) {
                int ix = x0 + dx;
                if (ix < 0 || ix >= W) continue;
                float wx = dx ? txf : (1.f - txf);
                float wgt = wy * wx * m;
                float4 v = *(const float4*)(valbase + (size_t)(iy * W + ix) * C);
                acc.x += v.x * wgt;
                acc.y += v.y * wgt;
                acc.z += v.z * wgt;
                acc.w += v.w * wgt;
            }
        }
    }

    float* o = g_samp + (size_t)(n * P + p) * C + g * CG + cq * 4;
    *(float4*)o = acc;
}

// ---------------------------------------------------------------------------
// GEMM 3 + bias + BN + SiLU, transposed store to (N,C,H,W)
// ---------------------------------------------------------------------------
__global__ __launch_bounds__(256, 1)
void gemm_out_kernel(const float* __restrict__ bout,
                     const float* __restrict__ gamma,
                     const float* __restrict__ beta,
                     const float* __restrict__ mean,
                     const float* __restrict__ var,
                     float* __restrict__ outp)
{
    extern __shared__ char sm[];
    uint32_t smb = smem_u32(sm);
    const int t = threadIdx.x, lane = t & 31, wid = t >> 5;
    const int mg0 = blockIdx.x * 128;

    // --- A: samp tile row-major -> bf16 hi/lo ---
    {
        const float* sa = g_samp + (size_t)mg0 * C;
#pragma unroll 4
        for (int i = t; i < 128 * 32; i += 256) {
            int m = i >> 5, kq = (i & 31) * 4;
            float4 v = *(const float4*)(sa + (size_t)m * C + kq);
            float hx = __bfloat162float(__float2bfloat16(v.x));
            float hy = __bfloat162float(__float2bfloat16(v.y));
            float hz = __bfloat162float(__float2bfloat16(v.z));
            float hw = __bfloat162float(__float2bfloat16(v.w));
            uint2 hp, lp;
            hp.x = pack_bf16(hx, hy);            hp.y = pack_bf16(hz, hw);
            lp.x = pack_bf16(v.x - hx, v.y - hy); lp.y = pack_bf16(v.z - hz, v.w - hw);
            uint32_t off = (uint32_t)(m * STRA + kq) * 2;
            *(uint2*)(sm + SM_AH + off) = hp;
            *(uint2*)(sm + SM_AL + off) = lp;
        }
    }
    load_B(sm, SM_BH, g_Bw_hi, 128, 0, t);
    load_B(sm, SM_BL, g_Bw_lo, 128, 0, t);
    __syncthreads();

    float acc[4][4][4];
#pragma unroll
    for (int a = 0; a < 4; a++)
#pragma unroll
        for (int b = 0; b < 4; b++)
#pragma unroll
            for (int r = 0; r < 4; r++) acc[a][b][r] = 0.f;

    gemm_core(smb, lane, wid, acc);

    // --- epilogue: bias + BN + SiLU, transposed store ---
    const int wm = wid & 1, wn = wid >> 1;
    const int gid = lane >> 2, tg = lane & 3;
    const int nimg = mg0 >> 12;
    const int pbase = (mg0 & 4095) + wm * 64;

#pragma unroll
    for (int nt = 0; nt < 4; nt++) {
        int c = wn * 32 + nt * 8 + 2 * tg;
        float iv0 = __ldg(&gamma[c])   * rsqrtf(__ldg(&var[c])   + 1e-5f);
        float iv1 = __ldg(&gamma[c+1]) * rsqrtf(__ldg(&var[c+1]) + 1e-5f);
        float ad0 = __ldg(&beta[c])   - __ldg(&mean[c])   * iv0;
        float ad1 = __ldg(&beta[c+1]) - __ldg(&mean[c+1]) * iv1;
        float bo0 = __ldg(&bout[c]), bo1 = __ldg(&bout[c+1]);
        float* out0 = outp + (size_t)(nimg * C + c)     * P;
        float* out1 = outp + (size_t)(nimg * C + c + 1) * P;
#pragma unroll
        for (int mi = 0; mi < 4; mi++) {
            int p = pbase + mi * 16 + gid;
            float v00 = (acc[mi][nt][0] + bo0) * iv0 + ad0;
            float v01 = (acc[mi][nt][1] + bo1) * iv1 + ad1;
            float v10 = (acc[mi][nt][2] + bo0) * iv0 + ad0;
            float v11 = (acc[mi][nt][3] + bo1) * iv1 + ad1;
            out0[p]     = v00 / (1.f + expf(-v00));
            out1[p]     = v01 / (1.f + expf(-v01));
            out0[p + 8] = v10 / (1.f + expf(-v10));
            out1[p + 8] = v11 / (1.f + expf(-v11));
        }
    }
}

// ---------------------------------------------------------------------------
extern "C" void kernel_launch(void* const* d_in, const int* in_sizes, int n_in,
                              void* d_out, int out_size)
{
    const float* x       = (const float*)d_in[0];
    const float* w_value = (const float*)d_in[1];
    const float* b_value = (const float*)d_in[2];
    const float* w_off   = (const float*)d_in[3];
    const float* b_off   = (const float*)d_in[4];
    const float* w_out   = (const float*)d_in[5];
    const float* b_out   = (const float*)d_in[6];
    const float* gamma   = (const float*)d_in[7];
    const float* beta    = (const float*)d_in[8];
    const float* mean    = (const float*)d_in[9];
    const float* var     = (const float*)d_in[10];
    float* out = (float*)d_out;

    cudaFuncSetAttribute(gemm_x_kernel,   cudaFuncAttributeMaxDynamicSharedMemorySize, SM_TOTAL);
    cudaFuncSetAttribute(gemm_out_kernel, cudaFuncAttributeMaxDynamicSharedMemorySize, SM_TOTAL);

    __nv_bfloat16 *bvh, *bvl, *boh, *bol, *bwh, *bwl;
    cudaGetSymbolAddress((void**)&bvh, g_Bv_hi);
    cudaGetSymbolAddress((void**)&bvl, g_Bv_lo);
    cudaGetSymbolAddress((void**)&boh, g_Bo_hi);
    cudaGetSymbolAddress((void**)&bol, g_Bo_lo);
    cudaGetSymbolAddress((void**)&bwh, g_Bw_hi);
    cudaGetSymbolAddress((void**)&bwl, g_Bw_lo);
    float *gval, *gom;
    cudaGetSymbolAddress((void**)&gval, g_val);
    cudaGetSymbolAddress((void**)&gom,  g_om);

    prep_kernel<<<256, 256>>>(w_value, w_off, w_out);
    gemm_x_kernel<<<dim3(MTOT/128, 1), 256, SM_TOTAL>>>(x, bvh, bvl, b_value, gval, 128);
    gemm_x_kernel<<<dim3(MTOT/128, 2), 256, SM_TOTAL>>>(x, boh, bol, b_off, gom, 256);
    sample_kernel<<<(NB * P * G * 4) / 256, 256>>>();
    gemm_out_kernel<<<MTOT/128, 256, SM_TOTAL>>>(b_out, gamma, beta, mean, var, out);
}